// round 17
// baseline (speedup 1.0000x reference)
#include <cuda_runtime.h>
#include <cuda_bf16.h>
#include <math.h>
#include <stdint.h>

// ---------------------------------------------------------------------------
#define NB   16
#define CIN  512
#define WID  128
#define OUP  512
#define HH   56
#define WW   56
#define HW   (HH*WW)
#define MIP  16

union U8 { __nv_bfloat16 h[8]; uint4 u; };

__device__ __forceinline__ uint32_t smem_u32(const void* p) {
    uint32_t a;
    asm("{ .reg .u64 t; cvta.to.shared.u64 t, %1; cvt.u32.u64 %0, t; }" : "=r"(a) : "l"(p));
    return a;
}
__device__ __forceinline__ void ldsm4(uint32_t* r, uint32_t a) {
    asm volatile("ldmatrix.sync.aligned.m8n8.x4.shared.b16 {%0,%1,%2,%3}, [%4];"
                 : "=r"(r[0]), "=r"(r[1]), "=r"(r[2]), "=r"(r[3]) : "r"(a));
}
__device__ __forceinline__ void mma_bf(float* c, const uint32_t* a, uint32_t b0, uint32_t b1) {
    asm volatile("mma.sync.aligned.m16n8k16.row.col.f32.bf16.bf16.f32 "
                 "{%0,%1,%2,%3}, {%4,%5,%6,%7}, {%8,%9}, {%0,%1,%2,%3};"
                 : "+f"(c[0]), "+f"(c[1]), "+f"(c[2]), "+f"(c[3])
                 : "r"(a[0]), "r"(a[1]), "r"(a[2]), "r"(a[3]), "r"(b0), "r"(b1));
}
__device__ __forceinline__ void cpa16(uint32_t d, const void* s, uint32_t srcsz) {
    asm volatile("cp.async.cg.shared.global [%0], [%1], 16, %2;"
                 :: "r"(d), "l"(s), "r"(srcsz) : "memory");
}
__device__ __forceinline__ void cpa_commit() { asm volatile("cp.async.commit_group;" ::: "memory"); }
template<int N> __device__ __forceinline__ void cpa_wait() {
    asm volatile("cp.async.wait_group %0;" :: "n"(N) : "memory");
}

// ---------------------------------------------------------------------------
// Scratch. gh1/gh2: DENSE stride-128 rows; compact values at cols 0..cnt-1,
// zeros after (never written -> static zero-init).
// ---------------------------------------------------------------------------
__device__ __align__(128) __nv_bfloat16 gh1_hi[NB*HW*WID];
__device__ __align__(128) __nv_bfloat16 gh1_lo[NB*HW*WID];
__device__ __align__(128) __nv_bfloat16 gh2_hi[NB*HW*WID];
__device__ __align__(128) __nv_bfloat16 gh2_lo[NB*HW*WID];
__device__ __align__(128) __nv_bfloat16 gw1h[WID*CIN],  gw1l[WID*CIN];
__device__ __align__(128) __nv_bfloat16 gw2bh[NB*WID*1152], gw2bl[NB*WID*1152]; // [b][om][r*128+cc]
__device__ __align__(128) __nv_bfloat16 gw3bh[NB*OUP*WID],  gw3bl[NB*OUP*WID];  // [b][om][cc]
__device__ __align__(16) float g_smlog[NB*HW];
__device__ __align__(16) float g_poolx[NB*CIN];
__device__ __align__(16) float g_pool1[NB*WID];
__device__ __align__(16) float g_pool2[NB*WID];
__device__ __align__(16) float g_ys   [NB*2*HH*MIP];
__device__ __align__(16) int   g_idx  [NB*HW];
__device__ __align__(16) int   g_cnt  [NB];
__device__ __align__(16) int   g_ocl1 [NB*WID];
__device__ __align__(16) int   g_ocl2 [NB*WID];
__device__ __align__(16) int   g_ocl3 [NB*OUP];
__device__ __align__(16) int   g_occ1 [NB];
__device__ __align__(16) int   g_occ2 [NB];
__device__ __align__(16) int   g_occ3 [NB];
__device__ __align__(16) float s_sm [NB*HW];
__device__ __align__(16) float s_smd[NB*HW];
__device__ __align__(16) float s_c1 [NB*WID];
__device__ __align__(16) float s_c2 [NB*WID];
__device__ __align__(16) float s_c3 [NB*OUP];
__device__ __align__(16) float s_xh [NB*OUP*HH];
__device__ __align__(16) float s_xw [NB*OUP*WW];
__device__ __align__(16) float s_ah [NB*OUP*HH];
__device__ __align__(16) float s_aw [NB*OUP*WW];

// ---------------------------------------------------------------------------
__global__ void kZ_zero()
{
    int i = blockIdx.x * 256 + threadIdx.x;
    if (i < NB*HW)  g_smlog[i] = 0.f;
    if (i < NB*CIN) g_poolx[i] = 0.f;
    if (i < NB*WID) { g_pool1[i] = 0.f; g_pool2[i] = 0.f; }
}

// ---------------------------------------------------------------------------
// kT: pure reduction over x: smask-logit partials (per pixel) + channel sums.
// ---------------------------------------------------------------------------
__global__ __launch_bounds__(256) void kT_reduce(const float* __restrict__ x,
                                                 const float* __restrict__ smw)
{
    __shared__ float ts[64][65];
    __shared__ float wsh[64];
    __shared__ float red[4][64];
    const int b  = blockIdx.z;
    const int c0 = blockIdx.y * 64;
    const int p0 = blockIdx.x * 64;
    const int t  = threadIdx.x;

    if (t < 64) wsh[t] = smw[c0 + t];
    {
        int ci = t >> 2, jg = (t & 3) * 16;
        const float* src = x + ((size_t)b * CIN + c0 + ci) * HW + p0 + jg;
        #pragma unroll
        for (int q = 0; q < 4; q++) {
            float4 f = *(const float4*)(src + q * 4);
            ts[ci][jg + q*4 + 0] = f.x; ts[ci][jg + q*4 + 1] = f.y;
            ts[ci][jg + q*4 + 2] = f.z; ts[ci][jg + q*4 + 3] = f.w;
        }
    }
    __syncthreads();
    {
        int g = t >> 6, pi = t & 63;
        float s = 0.f;
        #pragma unroll
        for (int cc = 0; cc < 16; cc++) s += ts[g*16 + cc][pi] * wsh[g*16 + cc];
        red[g][pi] = s;
    }
    __syncthreads();
    if (t < 64)
        atomicAdd(&g_smlog[b * HW + p0 + t], red[0][t] + red[1][t] + red[2][t] + red[3][t]);
    __syncthreads();
    {
        int c = t & 63, pg = t >> 6;
        float s = 0.f;
        #pragma unroll
        for (int i = 0; i < 16; i++) s += ts[c][pg*16 + i];
        red[pg][c] = s;
    }
    __syncthreads();
    if (t < 64)
        atomicAdd(&g_poolx[b * CIN + c0 + t], red[0][t] + red[1][t] + red[2][t] + red[3][t]);
}

// ---------------------------------------------------------------------------
__global__ void kW1_split(const float* __restrict__ W)
{
    int i = blockIdx.x * 256 + threadIdx.x;
    if (i >= WID * CIN) return;
    float v = W[i];
    __nv_bfloat16 h = __float2bfloat16(v);
    gw1h[i] = h;
    gw1l[i] = __float2bfloat16(v - __bfloat162float(h));
}

// ---------------------------------------------------------------------------
// kB: threshold smask logits + 3x3 dilation.  grid (NB, 7).
// ---------------------------------------------------------------------------
__global__ __launch_bounds__(256) void kB_dilate(const float* __restrict__ smb)
{
    __shared__ float s[10][WW];
    int b  = blockIdx.x;
    int r0 = blockIdx.y * 8;
    float sb0 = smb[0];
    for (int i = threadIdx.x; i < 10 * WW; i += 256) {
        int rr = i / WW, cc = i - rr * WW;
        int gr = r0 + rr - 1;
        float m = 0.f;
        if (gr >= 0 && gr < HH)
            m = (g_smlog[b*HW + gr*WW + cc] + sb0) > 0.f ? 1.f : 0.f;
        s[rr][cc] = m;
    }
    __syncthreads();
    for (int i = threadIdx.x; i < 8 * WW; i += 256) {
        int rr = i / WW, cc = i - rr * WW;
        s_sm[b*HW + (r0+rr)*WW + cc] = s[rr+1][cc];
        float m = 0.f;
        #pragma unroll
        for (int dy = 0; dy < 3; dy++) {
            #pragma unroll
            for (int dx = -1; dx <= 1; dx++) {
                int xx = cc + dx; if (xx < 0 || xx >= WW) continue;
                m = fmaxf(m, s[rr+dy][xx]);
            }
        }
        s_smd[b*HW + (r0+rr)*WW + cc] = m;
    }
}

// ---------------------------------------------------------------------------
// kL_list: ordered compaction of s_sm=1 pixels.
// ---------------------------------------------------------------------------
__global__ __launch_bounds__(256) void kL_list()
{
    __shared__ int wsum[8], wbase[8], total;
    const int b = blockIdx.x, t = threadIdx.x;
    const int wrp = t >> 5, lane = t & 31;
    if (t == 0) total = 0;
    __syncthreads();
    for (int i0 = 0; i0 < HW; i0 += 256) {
        int i = i0 + t;
        int f = (i < HW) ? (s_sm[b*HW + i] > 0.5f ? 1 : 0) : 0;
        unsigned bal = __ballot_sync(0xffffffffu, f);
        int wp = __popc(bal & ((1u << lane) - 1u));
        if (lane == 0) wsum[wrp] = __popc(bal);
        __syncthreads();
        if (t == 0) {
            int acc = total;
            #pragma unroll
            for (int w = 0; w < 8; w++) { wbase[w] = acc; acc += wsum[w]; }
            total = acc;
        }
        __syncthreads();
        if (f) g_idx[b*HW + wbase[wrp] + wp] = i;
        __syncthreads();
    }
    if (t == 0) g_cnt[b] = total;
}

// ---------------------------------------------------------------------------
// kDL: fused channel-mask compute + ordered compaction.  grid NB.
// ---------------------------------------------------------------------------
template<int STAGE>
__global__ __launch_bounds__(256) void kDL(const float* __restrict__ w,
                                           const float* __restrict__ bias)
{
    constexpr int CI = (STAGE == 1) ? CIN : WID;
    constexpr int CO = (STAGE == 3) ? OUP : WID;
    const float* psum = (STAGE == 1) ? g_poolx : (STAGE == 2 ? g_pool1 : g_pool2);
    float*       mask = (STAGE == 1) ? s_c1 : (STAGE == 2 ? s_c2 : s_c3);
    int* list = (STAGE == 1) ? g_ocl1 : (STAGE == 2 ? g_ocl2 : g_ocl3);
    int* cnto = (STAGE == 1) ? g_occ1 : (STAGE == 2 ? g_occ2 : g_occ3);
    __shared__ float pr[CI];
    __shared__ float mk[CO];
    __shared__ int wsum[8], wbase[8], total;
    const int b = blockIdx.x, t = threadIdx.x;
    const int wrp = t >> 5, lane = t & 31;

    for (int i = t; i < CI; i += 256) pr[i] = psum[b*CI + i] * (1.f / HW);
    if (t == 0) total = 0;
    __syncthreads();
    for (int o = wrp; o < CO; o += 8) {
        const float* wr = w + (size_t)o * CI;
        float s = 0.f;
        #pragma unroll 4
        for (int c = lane; c < CI; c += 32) s += pr[c] * wr[c];
        #pragma unroll
        for (int off = 16; off > 0; off >>= 1) s += __shfl_xor_sync(0xffffffffu, s, off);
        if (lane == 0) {
            float mv = (s + bias[o]) > 0.f ? 1.f : 0.f;
            mask[b*CO + o] = mv;
            mk[o] = mv;
        }
    }
    __syncthreads();
    for (int i0 = 0; i0 < CO; i0 += 256) {
        int i = i0 + t;
        int f = (i < CO) ? (mk[i] > 0.5f ? 1 : 0) : 0;
        unsigned bal = __ballot_sync(0xffffffffu, f);
        int wp = __popc(bal & ((1u << lane) - 1u));
        if (lane == 0) wsum[wrp] = __popc(bal);
        __syncthreads();
        if (t == 0) {
            int acc = total;
            #pragma unroll
            for (int w2 = 0; w2 < 8; w2++) { wbase[w2] = acc; acc += wsum[w2]; }
            total = acc;
        }
        __syncthreads();
        if (f) list[b*CO + wbase[wrp] + wp] = i;
        __syncthreads();
    }
    if (t == 0) cnto[b] = total;
}

// ---------------------------------------------------------------------------
// kG2 / kG3: per-batch gathered + split conv2/conv3 weights (fixed strides).
// ---------------------------------------------------------------------------
__global__ __launch_bounds__(256) void kG2(const float* __restrict__ W2)
{
    const int b  = blockIdx.y;
    const int c1 = g_occ1[b];
    const int c2 = g_occ2[b];
    const int M2p = (c2 + 63) & ~63;
    const int tot = M2p * 1152;
    for (int e = blockIdx.x * 256 + threadIdx.x; e < tot; e += gridDim.x * 256) {
        int om = e / 1152, rem = e - om * 1152;
        int r = rem >> 7, cc = rem & 127;
        float v = 0.f;
        if (om < c2 && cc < c1) {
            int o = g_ocl2[b*WID + om];
            int c = g_ocl1[b*WID + cc];
            v = W2[(size_t)o * 1152 + c * 9 + r];
        }
        __nv_bfloat16 h = __float2bfloat16(v);
        gw2bh[(size_t)b*WID*1152 + e] = h;
        gw2bl[(size_t)b*WID*1152 + e] = __float2bfloat16(v - __bfloat162float(h));
    }
}

__global__ __launch_bounds__(256) void kG3(const float* __restrict__ W3)
{
    const int b  = blockIdx.y;
    const int c2 = g_occ2[b];
    const int c3 = g_occ3[b];
    const int M3p = (c3 + 63) & ~63;
    const int tot = M3p * 128;
    for (int e = blockIdx.x * 256 + threadIdx.x; e < tot; e += gridDim.x * 256) {
        int om = e >> 7, cc = e & 127;
        float v = 0.f;
        if (om < c3 && cc < c2) {
            int o = g_ocl3[b*OUP + om];
            int c = g_ocl2[b*WID + cc];
            v = W3[(size_t)o * WID + c];
        }
        __nv_bfloat16 h = __float2bfloat16(v);
        gw3bh[(size_t)b*OUP*WID + e] = h;
        gw3bl[(size_t)b*OUP*WID + e] = __float2bfloat16(v - __bfloat162float(h));
    }
}

// ---------------------------------------------------------------------------
// conv_mma: compacted bf16-split GEMM.
// MODE 1: reads x fp32 directly, stages [32c][128px] + in-kernel split/transpose;
//         oc by list1 -> gh1 compact cols; pm=smd; +pool1
// MODE 2: chunks r(0..8)xKC1; px by g_idx; oc by list2 -> gh2 compact; pm=1
// MODE 3: chunks KC2; oc by list3 -> d_out rows list3; pm=s_sm
// ---------------------------------------------------------------------------
#define A_HI 0
#define A_LO 10240
#define B_HI 20480
#define B_LO 25600
#define STG  30720
#define XS_OFF (2*STG)
#define XS_STG 16896
#define CONV_DSM  (2*STG)
#define CONV1_DSM (2*STG + 2*XS_STG)

template<int MODE>
__global__ __launch_bounds__(256, 2)
void conv_mma(const float* __restrict__ bias,
              const float* __restrict__ xin,
              float* __restrict__ xout)
{
    extern __shared__ char dsm[];
    const uint32_t sb = smem_u32(dsm);
    __shared__ float pmv[128], cmb[64], bb[64];
    __shared__ float pool[64];
    __shared__ int   pidx[128];
    __shared__ int   ocl_s[64];

    const int tid  = threadIdx.x;
    const int wid  = tid >> 5;
    const int lane = tid & 31;
    const int b    = blockIdx.z;
    const int m0   = blockIdx.x * 128;
    const int n0g  = blockIdx.y * 64;

    const int cnt1 = g_occ1[b];
    const int cnt2 = (MODE >= 2) ? g_occ2[b] : 0;
    const int KC1  = (cnt1 + 31) >> 5;
    const int KC2  = (cnt2 + 31) >> 5;

    const int ocnt = (MODE == 1) ? cnt1 : (MODE == 2 ? cnt2 : g_occ3[b]);
    if (n0g >= ocnt) return;
    const int cntpx = (MODE == 2) ? g_cnt[b] : HW;
    if (MODE == 2 && m0 >= cntpx) return;

    const int NCr = (MODE == 1) ? 16 : (MODE == 2 ? 9 * KC1 : (KC2 > 0 ? KC2 : 1));

    const __nv_bfloat16* act_h = (MODE == 2) ? gh1_hi : gh2_hi;
    const __nv_bfloat16* act_l = (MODE == 2) ? gh1_lo : gh2_lo;
    const __nv_bfloat16* wt_h  = (MODE == 1) ? gw1h : (MODE == 2 ? gw2bh + (size_t)b*WID*1152
                                                                 : gw3bh + (size_t)b*OUP*WID);
    const __nv_bfloat16* wt_l  = (MODE == 1) ? gw1l : (MODE == 2 ? gw2bl + (size_t)b*WID*1152
                                                                 : gw3bl + (size_t)b*OUP*WID);
    const int Bstr = (MODE == 1) ? CIN : (MODE == 2 ? 1152 : 128);

    if (tid < 128) {
        int n = m0 + tid;
        if (MODE == 2) {
            pidx[tid] = (n < cntpx) ? g_idx[b * HW + n] : 0;
            pmv[tid]  = 1.f;
        } else {
            const float* pm = (MODE == 1) ? s_smd : s_sm;
            pmv[tid] = (n < HW) ? pm[b * HW + n] : 0.f;
        }
    }
    if (tid < 64) {
        int oc = n0g + tid;
        bool v = (oc < ocnt);
        const int* list = (MODE == 1) ? g_ocl1 : (MODE == 2 ? g_ocl2 : g_ocl3);
        int tc = v ? list[b * ((MODE == 3) ? OUP : WID) + oc] : 0;
        ocl_s[tid] = tc;
        bb[tid]  = v ? bias[tc] : 0.f;
        cmb[tid] = v ? 1.f : 0.f;
        pool[tid] = 0.f;
    }
    __syncthreads();

    const int prow = tid >> 1;
    const int u0   = (tid & 1) * 2;
    const int brow2 = tid >> 2;
    const int bu    = tid & 3;
    // MODE 1 staging mapping
    const int xc  = tid >> 3;            // 0..31 channel row
    const int xg0 = (tid & 7) * 4;       // 16B units, 4 each

    auto prefetch = [&](int ch, int st) {
        const uint32_t sbase = sb + st * STG;
        int c0, koff;
        int r = 0;
        if (MODE == 1)      { c0 = ch * 32; koff = c0; }
        else if (MODE == 2) { r = ch / KC1; int kc = ch - r * KC1; c0 = kc * 32; koff = r * 128 + c0; }
        else                { c0 = ch * 32; koff = c0; }
        // A operand
        if (MODE == 1) {
            // stage x fp32 [32c][128px] -> XS
            const float* xrow = xin + ((size_t)b * CIN + c0 + xc) * HW;
            uint32_t dxs = sb + XS_OFF + st * XS_STG + xc * 528 + xg0 * 16;
            #pragma unroll
            for (int u = 0; u < 4; u++) {
                int g   = xg0 + u;
                int px0 = m0 + g * 4;
                uint32_t sz = (px0 + 4 <= HW) ? 16u : 0u;
                int pxs = (px0 + 4 <= HW) ? px0 : 0;
                cpa16(dxs + u * 16, xrow + pxs, sz);
            }
        } else {
            int n = m0 + prow;
            bool valid; int q;
            if (MODE == 2) {
                bool vrow = (n < cntpx);
                int p = vrow ? pidx[prow] : 0;
                int ky = r / 3 - 1, kx = r % 3 - 1;
                int py = p / WW, px = p - py * WW;
                int iy = py + ky, ix = px + kx;
                valid = vrow && iy >= 0 && iy < HH && ix >= 0 && ix < WW;
                q = iy * WW + ix;
            } else { valid = (n < HW); q = n; }
            uint32_t sz = valid ? 16u : 0u;
            const __nv_bfloat16* ah = act_h + ((size_t)b * HW + (valid ? q : 0)) * WID + c0 + u0 * 8;
            const __nv_bfloat16* al = act_l + ((size_t)b * HW + (valid ? q : 0)) * WID + c0 + u0 * 8;
            uint32_t dh = sbase + A_HI + prow * 80 + u0 * 16;
            uint32_t dl = sbase + A_LO + prow * 80 + u0 * 16;
            #pragma unroll
            for (int u = 0; u < 2; u++) {
                cpa16(dh + u * 16, ah + u * 8, sz);
                cpa16(dl + u * 16, al + u * 8, sz);
            }
        }
        // B operand (weights)
        {
            size_t rowoff;
            if (MODE == 1) rowoff = (size_t)ocl_s[brow2] * CIN;
            else           rowoff = (size_t)(n0g + brow2) * Bstr;
            cpa16(sbase + B_HI + brow2 * 80 + bu * 16, wt_h + rowoff + koff + bu * 8, 16u);
            cpa16(sbase + B_LO + brow2 * 80 + bu * 16, wt_l + rowoff + koff + bu * 8, 16u);
        }
        cpa_commit();
    };

    float cacc[2][4][4];
    #pragma unroll
    for (int i = 0; i < 2; i++)
        #pragma unroll
        for (int j = 0; j < 4; j++)
            #pragma unroll
            for (int q = 0; q < 4; q++) cacc[i][j][q] = 0.f;

    const int wm = wid >> 1, wn = wid & 1;
    const int lr = lane & 7, s23 = lane >> 3;
    const int arow = (s23 & 1) * 8 + lr, acol = (s23 >> 1) * 8;
    const int brow = (s23 >> 1) * 8 + lr, bcol = (s23 & 1) * 8;

    prefetch(0, 0);
    int buf = 0;
    for (int ch = 0; ch < NCr; ch++) {
        cpa_wait<0>();
        __syncthreads();
        if (MODE == 1) {
            // convert XS[buf] -> A tiles [buf] (split + transpose)
            const float* xs = (const float*)(dsm + XS_OFF + buf * XS_STG);
            const int p   = tid >> 1;
            const int ch0 = (tid & 1) * 16;
            #pragma unroll
            for (int half = 0; half < 2; half++) {
                U8 hh, ll;
                #pragma unroll
                for (int j = 0; j < 8; j++) {
                    float v = xs[(ch0 + half * 8 + j) * 132 + p];
                    __nv_bfloat16 h = __float2bfloat16(v);
                    hh.h[j] = h;
                    ll.h[j] = __float2bfloat16(v - __bfloat162float(h));
                }
                uint32_t off = (uint32_t)(p * 80 + ch0 * 2 + half * 16);
                *(uint4*)(dsm + buf * STG + A_HI + off) = hh.u;
                *(uint4*)(dsm + buf * STG + A_LO + off) = ll.u;
            }
            __syncthreads();
        }
        if (ch + 1 < NCr) prefetch(ch + 1, buf ^ 1);

        const uint32_t sbb = sb + buf * STG;
        #pragma unroll
        for (int s = 0; s < 2; s++) {
            const int kb = s * 16;
            uint32_t ah[2][4], al[2][4];
            #pragma unroll
            for (int mi = 0; mi < 2; mi++) {
                uint32_t off = (uint32_t)((wm * 32 + mi * 16 + arow) * 80 + (kb + acol) * 2);
                ldsm4(ah[mi], sbb + A_HI + off);
                ldsm4(al[mi], sbb + A_LO + off);
            }
            #pragma unroll
            for (int np = 0; np < 2; np++) {
                uint32_t bh[4], bl[4];
                uint32_t off = (uint32_t)((wn * 32 + np * 16 + brow) * 80 + (kb + bcol) * 2);
                ldsm4(bh, sbb + B_HI + off);
                ldsm4(bl, sbb + B_LO + off);
                #pragma unroll
                for (int mi = 0; mi < 2; mi++) {
                    mma_bf(cacc[mi][np * 2],     ah[mi], bh[0], bh[1]);
                    mma_bf(cacc[mi][np * 2 + 1], ah[mi], bh[2], bh[3]);
                }
                #pragma unroll
                for (int mi = 0; mi < 2; mi++) {
                    mma_bf(cacc[mi][np * 2],     al[mi], bh[0], bh[1]);
                    mma_bf(cacc[mi][np * 2 + 1], al[mi], bh[2], bh[3]);
                }
                #pragma unroll
                for (int mi = 0; mi < 2; mi++) {
                    mma_bf(cacc[mi][np * 2],     ah[mi], bl[0], bl[1]);
                    mma_bf(cacc[mi][np * 2 + 1], ah[mi], bl[2], bl[3]);
                }
            }
        }
        buf ^= 1;
    }

    // ---- epilogue ----
    const int g = lane >> 2, tg = lane & 3;
    if (MODE != 3) {
        __nv_bfloat16* ohg = (MODE == 1 ? gh1_hi : gh2_hi);
        __nv_bfloat16* olg = (MODE == 1 ? gh1_lo : gh2_lo);
        float lsum[8];
        #pragma unroll
        for (int i = 0; i < 8; i++) lsum[i] = 0.f;
        #pragma unroll
        for (int mi = 0; mi < 2; mi++) {
            #pragma unroll
            for (int h = 0; h < 2; h++) {
                int pl = wm * 32 + mi * 16 + g + h * 8;
                int n  = m0 + pl;
                bool store = (MODE == 2) ? (n < cntpx) : (n < HW);
                if (store) {
                    int p = (MODE == 2) ? pidx[pl] : n;
                    float pmx = pmv[pl];
                    size_t rowoff = ((size_t)b * HW + p) * WID;
                    #pragma unroll
                    for (int nf = 0; nf < 4; nf++) {
                        int ocl = wn * 32 + nf * 8 + tg * 2;
                        float v0 = fmaxf(cacc[mi][nf][h*2+0] + bb[ocl],   0.f) * cmb[ocl]   * pmx;
                        float v1 = fmaxf(cacc[mi][nf][h*2+1] + bb[ocl+1], 0.f) * cmb[ocl+1] * pmx;
                        lsum[nf*2 + 0] += v0;
                        lsum[nf*2 + 1] += v1;
                        __nv_bfloat16 h0 = __float2bfloat16(v0);
                        __nv_bfloat16 h1 = __float2bfloat16(v1);
                        __nv_bfloat162 hp; hp.x = h0; hp.y = h1;
                        *(__nv_bfloat162*)(ohg + rowoff + n0g + ocl) = hp;
                        __nv_bfloat162 lp;
                        lp.x = __float2bfloat16(v0 - __bfloat162float(h0));
                        lp.y = __float2bfloat16(v1 - __bfloat162float(h1));
                        *(__nv_bfloat162*)(olg + rowoff + n0g + ocl) = lp;
                    }
                }
            }
        }
        #pragma unroll
        for (int nf = 0; nf < 4; nf++) {
            int ocl = wn * 32 + nf * 8 + tg * 2;
            atomicAdd(&pool[ocl],     lsum[nf*2 + 0]);
            atomicAdd(&pool[ocl + 1], lsum[nf*2 + 1]);
        }
        __syncthreads();
        float* gpool = (MODE == 1) ? g_pool1 : g_pool2;
        if (tid < 64 && n0g + tid < ocnt)
            atomicAdd(&gpool[b * WID + ocl_s[tid]], pool[tid]);
    } else {
        float* tf = (float*)dsm;
        __syncthreads();
        #pragma unroll
        for (int mi = 0; mi < 2; mi++)
            #pragma unroll
            for (int h = 0; h < 2; h++) {
                int pl = wm * 32 + mi * 16 + g + h * 8;
                float pmx = pmv[pl];
                #pragma unroll
                for (int nf = 0; nf < 4; nf++) {
                    int ocl = wn * 32 + nf * 8 + tg * 2;
                    tf[ocl * 132 + pl]       = (cacc[mi][nf][h*2+0] + bb[ocl])   * cmb[ocl]   * pmx;
                    tf[(ocl + 1) * 132 + pl] = (cacc[mi][nf][h*2+1] + bb[ocl+1]) * cmb[ocl+1] * pmx;
                }
            }
        __syncthreads();
        int ocl = tid >> 2, q = tid & 3;
        if (n0g + ocl < ocnt && m0 + q * 32 < HW) {
            float* orow = xout + ((size_t)b * OUP + ocl_s[ocl]) * HW + m0 + q * 32;
            const float* src = tf + ocl * 132 + q * 32;
            #pragma unroll
            for (int gi = 0; gi < 8; gi++)
                *(float4*)(orow + gi * 4) = *(const float4*)(src + gi * 4);
        }
    }
}

// ---------------------------------------------------------------------------
// kH: row/col means; cm3=0 rows are zero without touching d_out (unwritten).
// ---------------------------------------------------------------------------
__global__ __launch_bounds__(256) void kH_rowcol(const float* __restrict__ h3)
{
    __shared__ float img[HW];
    int bc = blockIdx.x;
    int t = threadIdx.x;
    if (s_c3[bc] < 0.5f) {
        if (t < WW) s_xw[bc * WW + t] = 0.f;
        if (t >= 64 && t < 64 + HH) s_xh[bc * HH + t - 64] = 0.f;
        return;
    }
    const float* src = h3 + (size_t)bc * HW;
    for (int i = t; i < HW; i += 256) img[i] = src[i];
    __syncthreads();
    if (t < WW) {
        float s = 0.f;
        #pragma unroll 8
        for (int h = 0; h < HH; h++) s += img[h * WW + t];
        s_xw[bc * WW + t] = s * (1.f / HH);
    } else if (t >= 64 && t < 64 + HH) {
        int r = t - 64;
        float s = 0.f;
        #pragma unroll 8
        for (int w = 0; w < WW; w++) s += img[r * WW + w];
        s_xh[bc * HH + r] = s * (1.f / WW);
    }
}

// ---------------------------------------------------------------------------
__global__ __launch_bounds__(256) void kI1(const float* __restrict__ w1,
                                           const float* __restrict__ b1)
{
    __shared__ float w1s[MIP * OUP];
    const int b = blockIdx.x;
    const int t = threadIdx.x;
    for (int i = t; i < MIP * OUP; i += 256) w1s[i] = w1[i];
    __syncthreads();
    const int wid = t >> 5, lane = t & 31;
    const int ti = blockIdx.y * 8 + wid;
    const float* src = (ti < HH)
        ? (s_xh + (size_t)b * OUP * HH + ti)
        : (s_xw + (size_t)b * OUP * WW + (ti - HH));
    float acc[MIP];
    #pragma unroll
    for (int m = 0; m < MIP; m++) acc[m] = 0.f;
    #pragma unroll 4
    for (int cc = 0; cc < 16; cc++) {
        int c = cc * 32 + lane;
        float v = src[(size_t)c * HH];
        #pragma unroll
        for (int m = 0; m < MIP; m++) acc[m] += v * w1s[m * OUP + c];
    }
    #pragma unroll
    for (int off = 16; off > 0; off >>= 1)
        #pragma unroll
        for (int m = 0; m < MIP; m++) acc[m] += __shfl_xor_sync(0xffffffffu, acc[m], off);
    if (lane == 0) {
        #pragma unroll
        for (int m = 0; m < MIP; m++) {
            float u = acc[m] + b1[m];
            float r6 = fminf(fmaxf(u + 3.f, 0.f), 6.f);
            g_ys[((size_t)b * 2 * HH + ti) * MIP + m] = u * r6 * (1.f / 6.f);
        }
    }
}

__global__ __launch_bounds__(256) void kI2(const float* __restrict__ wh,
                                           const float* __restrict__ bh,
                                           const float* __restrict__ ww,
                                           const float* __restrict__ bw)
{
    __shared__ float ys[2 * HH * MIP];
    const int b  = blockIdx.x;
    const int c0 = blockIdx.y * 64;
    const int t  = threadIdx.x;
    for (int i = t; i < 2 * HH * MIP; i += 256) ys[i] = g_ys[(size_t)b * 2 * HH * MIP + i];
    __syncthreads();
    const int cl = t >> 2, jq = t & 3;
    const int c  = c0 + cl;
    float whr[MIP], wwr[MIP];
    #pragma unroll
    for (int m = 0; m < MIP; m++) { whr[m] = wh[c*MIP + m]; wwr[m] = ww[c*MIP + m]; }
    const float bhc = bh[c], bwc = bw[c];
    #pragma unroll 2
    for (int jj = 0; jj < 14; jj++) {
        int j = jq * 14 + jj;
        float sh = bhc, sw = bwc;
        #pragma unroll
        for (int m = 0; m < MIP; m++) {
            sh += ys[j * MIP + m]        * whr[m];
            sw += ys[(HH + j) * MIP + m] * wwr[m];
        }
        s_ah[((size_t)b * OUP + c) * HH + j] = 1.f / (1.f + expf(-sh));
        s_aw[((size_t)b * OUP + c) * WW + j] = 1.f / (1.f + expf(-sw));
    }
}

// ---------------------------------------------------------------------------
// kJ: out = relu(h3*m3*ah*aw + x); masked rows skip the h3 read entirely.
// ---------------------------------------------------------------------------
__global__ void kJ_final(const float* __restrict__ x, float* __restrict__ out)
{
    size_t i = (size_t)blockIdx.x * blockDim.x + threadIdx.x;
    const size_t total4 = (size_t)NB * OUP * HW / 4;
    if (i >= total4) return;
    size_t e   = i * 4;
    size_t row = e / WW;
    int    w   = (int)(e - row * WW);
    size_t bc  = row / HH;
    float4 xv = *(const float4*)(x + e);
    float4 r;
    if (s_c3[bc] < 0.5f) {
        r.x = fmaxf(xv.x, 0.f);
        r.y = fmaxf(xv.y, 0.f);
        r.z = fmaxf(xv.z, 0.f);
        r.w = fmaxf(xv.w, 0.f);
    } else {
        float a_h  = s_ah[row];
        const float* awp = s_aw + bc * WW + w;
        float4 hv = *(float4*)(out + e);
        r.x = fmaxf(hv.x * a_h * awp[0] + xv.x, 0.f);
        r.y = fmaxf(hv.y * a_h * awp[1] + xv.y, 0.f);
        r.z = fmaxf(hv.z * a_h * awp[2] + xv.z, 0.f);
        r.w = fmaxf(hv.w * a_h * awp[3] + xv.w, 0.f);
    }
    *(float4*)(out + e) = r;
}

// ---------------------------------------------------------------------------
extern "C" void kernel_launch(void* const* d_in, const int* in_sizes, int n_in,
                              void* d_out, int out_size)
{
    const float* x     = (const float*)d_in[0];
    const float* sm_w  = (const float*)d_in[1];
    const float* sm_b  = (const float*)d_in[2];
    const float* cm1_w = (const float*)d_in[3];
    const float* cm1_b = (const float*)d_in[4];
    const float* cm2_w = (const float*)d_in[5];
    const float* cm2_b = (const float*)d_in[6];
    const float* cm3_w = (const float*)d_in[7];
    const float* cm3_b = (const float*)d_in[8];
    const float* w1    = (const float*)d_in[9];
    const float* b1    = (const float*)d_in[10];
    const float* w2    = (const float*)d_in[11];
    const float* b2    = (const float*)d_in[12];
    const float* w3    = (const float*)d_in[13];
    const float* b3    = (const float*)d_in[14];
    const float* ca_w1 = (const float*)d_in[15];
    const float* ca_b1 = (const float*)d_in[16];
    const float* ca_wh = (const float*)d_in[17];
    const float* ca_bh = (const float*)d_in[18];
    const float* ca_ww = (const float*)d_in[19];
    const float* ca_bw = (const float*)d_in[20];
    float* out = (float*)d_out;

    cudaFuncSetAttribute(conv_mma<1>, cudaFuncAttributeMaxDynamicSharedMemorySize, CONV1_DSM);
    cudaFuncSetAttribute(conv_mma<2>, cudaFuncAttributeMaxDynamicSharedMemorySize, CONV_DSM);
    cudaFuncSetAttribute(conv_mma<3>, cudaFuncAttributeMaxDynamicSharedMemorySize, CONV_DSM);

    kZ_zero<<<(NB*HW + 255)/256, 256>>>();
    kT_reduce<<<dim3(HW/64, CIN/64, NB), 256>>>(x, sm_w);
    kW1_split<<<(WID*CIN + 255)/256, 256>>>(w1);
    kB_dilate<<<dim3(NB, 7), 256>>>(sm_b);
    kL_list<<<NB, 256>>>();
    kDL<1><<<NB, 256>>>(cm1_w, cm1_b);

    conv_mma<1><<<dim3(25, 2, NB), 256, CONV1_DSM>>>(b1, x, out);

    kDL<2><<<NB, 256>>>(cm2_w, cm2_b);
    kG2<<<dim3(64, NB), 256>>>(w2);

    conv_mma<2><<<dim3(25, 2, NB), 256, CONV_DSM>>>(b2, x, out);

    kDL<3><<<NB, 256>>>(cm3_w, cm3_b);
    kG3<<<dim3(32, NB), 256>>>(w3);

    conv_mma<3><<<dim3(25, 8, NB), 256, CONV_DSM>>>(b3, x, out);

    kH_rowcol<<<NB * OUP, 256>>>(out);
    kI1<<<dim3(NB, 14), 256>>>(ca_w1, ca_b1);
    kI2<<<dim3(NB, 8),  256>>>(ca_wh, ca_bh, ca_ww, ca_bw);

    {
        size_t total4 = (size_t)NB * OUP * HW / 4;
        kJ_final<<<(unsigned)((total4 + 255) / 256), 256>>>(x, out);
    }
}